// round 9
// baseline (speedup 1.0000x reference)
#include <cuda_runtime.h>
#include <cuda_bf16.h>
#include <cstdint>

// ---------------------------------------------------------------------------
// GMDTW (soft-DTW, gamma=1), m1=m2=2048, d=128. log2-domain DP.
// R9: 64 single-warp CTAs x 32 rows (1 row/lane) -> 4 MUFU/iter, ~16 instr,
//     chain ~90 cyc. Same proven release/acquire flag pipeline as R8.
// ---------------------------------------------------------------------------

#define M1 2048
#define M2 2048
#define DIM 128
#define NCTA 64
#define CPITCH 2080          // floats per diagonal row of Cd
#define CROWS  4120          // diagonal rows (k) incl. prefetch overrun pad
#define BIGF 1e30f
#define INV_LN2 1.44269504088896340736f
#define LN2F    0.69314718055994530942f

__device__ float g_Cd[(size_t)CROWS * CPITCH];  // Cd[k][r] = C[r][k-r-2]*INV_LN2
__device__ float g_n1[M1];
__device__ float g_n2[M2];
__device__ float g_bnd[NCTA][4240];             // g_bnd[w][k] = R~[row 32(w+1)] @ diag k
__device__ int   g_prog[NCTA * 32];             // flag per 128B

__device__ __forceinline__ float ex2f(float x) {
    float r; asm("ex2.approx.f32 %0, %1;" : "=f"(r) : "f"(x)); return r;
}
__device__ __forceinline__ float lg2f(float x) {
    float r; asm("lg2.approx.f32 %0, %1;" : "=f"(r) : "f"(x)); return r;
}
__device__ __forceinline__ int acq_load(const int* p) {
    int v; asm volatile("ld.global.acquire.gpu.b32 %0, [%1];" : "=r"(v) : "l"(p) : "memory");
    return v;
}
__device__ __forceinline__ void rel_store(int* p, int v) {
    asm volatile("st.global.release.gpu.b32 [%0], %1;" :: "l"(p), "r"(v) : "memory");
}
__device__ __forceinline__ float4 ldcg4(const float* p) {
    float4 v;
    asm volatile("ld.global.cg.v4.f32 {%0,%1,%2,%3}, [%4];"
                 : "=f"(v.x), "=f"(v.y), "=f"(v.z), "=f"(v.w) : "l"(p) : "memory");
    return v;
}
__device__ __forceinline__ void stcg4(float* p, float4 v) {
    asm volatile("st.global.cg.v4.f32 [%0], {%1,%2,%3,%4};"
                 :: "l"(p), "f"(v.x), "f"(v.y), "f"(v.z), "f"(v.w) : "memory");
}

// ---------------------------------------------------------------------------
// init: fill Cd with BIG, reset flags
__global__ void __launch_bounds__(1024) initc_k() {
    size_t idx = (size_t)blockIdx.x * 1024 + threadIdx.x;
    const size_t n4 = (size_t)CROWS * CPITCH / 4;
    if (idx < n4) {
        ((float4*)g_Cd)[idx] = make_float4(BIGF, BIGF, BIGF, BIGF);
    }
    if (idx < NCTA * 32) g_prog[idx] = 0;
}

__global__ void __launch_bounds__(256) norms_k(const float* __restrict__ y,
                                               const float* __restrict__ x2) {
    int w = blockIdx.x * 8 + (threadIdx.x >> 5);
    int lane = threadIdx.x & 31;
    if (w >= 2 * M1) return;
    const float* src = (w < M1) ? (y + (size_t)w * DIM) : (x2 + (size_t)(w - M1) * DIM);
    float4 v = ((const float4*)src)[lane];
    float s = v.x * v.x + v.y * v.y + v.z * v.z + v.w * v.w;
#pragma unroll
    for (int o = 16; o; o >>= 1) s += __shfl_xor_sync(0xffffffffu, s, o);
    if (lane == 0) {
        if (w < M1) g_n1[w] = s; else g_n2[w - M1] = s;
    }
}

// GEMM with diagonal-major scatter epilogue:
// value for (r, c) goes to Cd[r+c+2][r]  (cell i=r+1, j=c+1, k=i+j)
__global__ void __launch_bounds__(256) gemm_k(const float* __restrict__ A,
                                              const float* __restrict__ B) {
    __shared__ float As[32][68];
    __shared__ float Bs[32][68];
    const int t  = threadIdx.x;
    const int tx = t & 15, ty = t >> 4;
    const int bi = blockIdx.y << 6, bj = blockIdx.x << 6;
    const int lrow = t >> 2;
    const int lk   = (t & 3) << 3;

    float acc[4][4];
#pragma unroll
    for (int u = 0; u < 4; ++u)
#pragma unroll
        for (int v = 0; v < 4; ++v) acc[u][v] = 0.0f;

    const float* Ap = A + (size_t)(bi + lrow) * DIM + lk;
    const float* Bp = B + (size_t)(bj + lrow) * DIM + lk;

    for (int k0 = 0; k0 < DIM; k0 += 32) {
        float4 a0 = *(const float4*)(Ap + k0);
        float4 a1 = *(const float4*)(Ap + k0 + 4);
        float4 b0 = *(const float4*)(Bp + k0);
        float4 b1 = *(const float4*)(Bp + k0 + 4);
        __syncthreads();
        As[lk + 0][lrow] = a0.x; As[lk + 1][lrow] = a0.y;
        As[lk + 2][lrow] = a0.z; As[lk + 3][lrow] = a0.w;
        As[lk + 4][lrow] = a1.x; As[lk + 5][lrow] = a1.y;
        As[lk + 6][lrow] = a1.z; As[lk + 7][lrow] = a1.w;
        Bs[lk + 0][lrow] = b0.x; Bs[lk + 1][lrow] = b0.y;
        Bs[lk + 2][lrow] = b0.z; Bs[lk + 3][lrow] = b0.w;
        Bs[lk + 4][lrow] = b1.x; Bs[lk + 5][lrow] = b1.y;
        Bs[lk + 6][lrow] = b1.z; Bs[lk + 7][lrow] = b1.w;
        __syncthreads();
#pragma unroll
        for (int kk = 0; kk < 32; ++kk) {
            float4 av = *(const float4*)&As[kk][ty << 2];
            float4 bv = *(const float4*)&Bs[kk][tx << 2];
            float a_[4] = {av.x, av.y, av.z, av.w};
            float b_[4] = {bv.x, bv.y, bv.z, bv.w};
#pragma unroll
            for (int u = 0; u < 4; ++u)
#pragma unroll
                for (int v = 0; v < 4; ++v) acc[u][v] += a_[u] * b_[v];
        }
    }

    float4 nb = *(const float4*)&g_n2[bj + (tx << 2)];
#pragma unroll
    for (int u = 0; u < 4; ++u) {
        int r = bi + (ty << 2) + u;
        float na = g_n1[r];
        float o0 = (na + nb.x - 2.0f * acc[u][0]) * INV_LN2;
        float o1 = (na + nb.y - 2.0f * acc[u][1]) * INV_LN2;
        float o2 = (na + nb.z - 2.0f * acc[u][2]) * INV_LN2;
        float o3 = (na + nb.w - 2.0f * acc[u][3]) * INV_LN2;
        int c = bj + (tx << 2);
        g_Cd[(size_t)(r + c + 2) * CPITCH + r] = o0;
        g_Cd[(size_t)(r + c + 3) * CPITCH + r] = o1;
        g_Cd[(size_t)(r + c + 4) * CPITCH + r] = o2;
        g_Cd[(size_t)(r + c + 5) * CPITCH + r] = o3;
    }
}

// ---------------------------------------------------------------------------
// DP wavefront: 64 single-warp CTAs, 32 rows/CTA, ONE row per lane.
// lane L owns row base+L+1 (1-based). Boundary row base comes from the
// predecessor CTA's lane 31. 261 groups of 8 diagonals.
__global__ void __launch_bounds__(32, 1) dp_k(float* __restrict__ out) {
    const int cta  = blockIdx.x;
    const int lane = threadIdx.x;
    const int base = cta * 32;
    const bool l0  = (lane == 0);
    const bool l31 = (lane == 31);

    // cost for row (base+lane) at diag k: Cd[k][base+lane]
    const float* pcost = g_Cd + (size_t)base * CPITCH + base + lane;

    const float4 BIG4 = make_float4(BIGF, BIGF, BIGF, BIGF);

    const int  wend    = (cta > 0) ? (base + 2048) : -1;  // last real chunk start
    const int  flagmax = wend + 3;
    int*       myflag  = &g_prog[cta * 32];
    const int* pflag   = &g_prog[((cta > 0) ? (cta - 1) : 0) * 32];
    const float* brow  = g_bnd[(cta > 0) ? (cta - 1) : 0];
    int known = -1000000;

    // boundary chunk ring for group g: c0=[g-4..g-1], c1=[g..g+3], c2=[g+4..g+7]
    float4 c0, c1, c2;
    if (cta > 0) {
        int need = base + 15 < flagmax ? base + 15 : flagmax;
        do { known = acq_load(pflag); } while (known < need);
        c0 = ldcg4(brow + base - 4);
        c1 = ldcg4(brow + base);
        c2 = ldcg4(brow + base + 4);
    } else {
        c0 = BIG4; c1 = BIG4; c2 = BIG4;
        c1.x = 0.0f;                       // virtual B[0] = R[0][0] = 0
    }

    float r1 = BIGF;                       // own row @ diag k-1
    float u  = BIGF;                       // carry: dg = up@(k-1)
    float res = BIGF;

    // cost ring: ring[p] holds cost for iter (current group start + p)
    float ring[8];
#pragma unroll
    for (int p = 0; p < 8; ++p)
        ring[p] = __ldg(pcost + (size_t)p * CPITCH);
    const float* pn = pcost + (size_t)8 * CPITCH;   // loads for next group

    int g = base;
    float q[8];

#pragma unroll 1
    for (int gi = 0; gi < 261; ++gi, g += 8) {
        // top: acquire in flight; load boundary chunks [g+8], [g+12]
        // (flag >= g+15 was ensured at end of previous group -> loads are safe)
        int fnew = (cta > 0) ? acq_load(pflag) : 0;
        float4 n1 = (g + 8  <= wend) ? ldcg4(brow + g + 8)  : BIG4;
        float4 n2 = (g + 12 <= wend) ? ldcg4(brow + g + 12) : BIG4;

#pragma unroll
        for (int p = 0; p < 8; ++p) {
            // boundary value B[k-1], k = g+p
            float bu = (p == 0) ? c0.w :
                       (p == 1) ? c1.x : (p == 2) ? c1.y :
                       (p == 3) ? c1.z : (p == 4) ? c1.w :
                       (p == 5) ? c2.x : (p == 6) ? c2.y : c2.z;

            float cost = ring[p];
            ring[p] = __ldg(pn + (size_t)p * CPITCH);   // iter k+8

            float sup = __shfl_up_sync(0xffffffffu, r1, 1);
            float up  = l0 ? bu : sup;

            float m  = fminf(fminf(r1, u), up);
            float d0 = m - up;
            float d1 = m - r1;
            float d2 = m - u;
            float x0 = ex2f(d0);
            float x1 = ex2f(d1);
            float x2v = ex2f(d2);
            float e  = (x0 + x1) + x2v;
            float nv = (cost + m) - lg2f(e);

            u  = up;
            r1 = nv;

            q[p] = r1;
            if (p == 0 && gi == 260) res = r1;    // k = base+2080 (cta63: 4096)
        }

        // publish B[g..g+7] (lane 31's row = base+32), then flag
        if (l31) {
            stcg4(&g_bnd[cta][g],     make_float4(q[0], q[1], q[2], q[3]));
            stcg4(&g_bnd[cta][g + 4], make_float4(q[4], q[5], q[6], q[7]));
            rel_store(myflag, g + 7);
        }

        // end: fold acquire; ensure next top's loads ([g+16],[g+20]) are published
        if (cta > 0) {
            if (fnew > known) known = fnew;
            int need = g + 23 < flagmax ? g + 23 : flagmax;
            while (known < need) known = acq_load(pflag);
        }

        // rotate boundary ring; advance cost pointer
        c0 = c2; c1 = n1; c2 = n2;
        pn += (size_t)8 * CPITCH;
    }

    if (cta == NCTA - 1 && l31) {
        out[0] = res * LN2F;
    }
}

// ---------------------------------------------------------------------------
extern "C" void kernel_launch(void* const* d_in, const int* in_sizes, int n_in,
                              void* d_out, int out_size) {
    const float* y  = (const float*)d_in[0];
    const float* x2 = (const float*)d_in[1];
    float* out = (float*)d_out;

    const int n4 = (CROWS * CPITCH) / 4;           // 2,142,400
    initc_k<<<(n4 + 1023) / 1024, 1024>>>();
    norms_k<<<512, 256>>>(y, x2);
    gemm_k<<<dim3(M2 / 64, M1 / 64), 256>>>(y, x2);
    dp_k<<<NCTA, 32>>>(out);
}

// round 10
// speedup vs baseline: 1.1085x; 1.1085x over previous
#include <cuda_runtime.h>
#include <cuda_bf16.h>
#include <cstdint>

// ---------------------------------------------------------------------------
// GMDTW (soft-DTW, gamma=1), m1=m2=2048, d=128. log2-domain DP.
// R10: 16 single-warp CTAs x 128 rows (4 rows/lane). T_iter is dominated by a
// fixed ~300cyc serialization (R8/R9 evidence) -> amortize it over 4 rows.
// One LDG.128/iter for costs, 1 shfl, proven release/acquire flag pipeline.
// ---------------------------------------------------------------------------

#define M1 2048
#define M2 2048
#define DIM 128
#define NCTA 16
#define RPL 4                // rows per lane
#define CPITCH 2080          // floats per diagonal row of Cd
#define CROWS  4120          // diagonal rows (k) incl. prefetch overrun pad
#define BIGF 1e30f
#define INV_LN2 1.44269504088896340736f
#define LN2F    0.69314718055994530942f

__device__ float g_Cd[(size_t)CROWS * CPITCH];  // Cd[k][r] = C[r][k-r-2]*INV_LN2
__device__ float g_n1[M1];
__device__ float g_n2[M2];
__device__ float g_bnd[NCTA][4240];             // g_bnd[w][k] = R~[row 128(w+1)] @ diag k
__device__ int   g_prog[NCTA * 32];             // flag per 128B

__device__ __forceinline__ float ex2f(float x) {
    float r; asm("ex2.approx.f32 %0, %1;" : "=f"(r) : "f"(x)); return r;
}
__device__ __forceinline__ float lg2f(float x) {
    float r; asm("lg2.approx.f32 %0, %1;" : "=f"(r) : "f"(x)); return r;
}
__device__ __forceinline__ int acq_load(const int* p) {
    int v; asm volatile("ld.global.acquire.gpu.b32 %0, [%1];" : "=r"(v) : "l"(p) : "memory");
    return v;
}
__device__ __forceinline__ void rel_store(int* p, int v) {
    asm volatile("st.global.release.gpu.b32 [%0], %1;" :: "l"(p), "r"(v) : "memory");
}
__device__ __forceinline__ float4 ldcg4(const float* p) {
    float4 v;
    asm volatile("ld.global.cg.v4.f32 {%0,%1,%2,%3}, [%4];"
                 : "=f"(v.x), "=f"(v.y), "=f"(v.z), "=f"(v.w) : "l"(p) : "memory");
    return v;
}
__device__ __forceinline__ void stcg4(float* p, float4 v) {
    asm volatile("st.global.cg.v4.f32 [%0], {%1,%2,%3,%4};"
                 :: "l"(p), "f"(v.x), "f"(v.y), "f"(v.z), "f"(v.w) : "memory");
}

// ---------------------------------------------------------------------------
__global__ void __launch_bounds__(1024) initc_k() {
    size_t idx = (size_t)blockIdx.x * 1024 + threadIdx.x;
    const size_t n4 = (size_t)CROWS * CPITCH / 4;
    if (idx < n4) {
        ((float4*)g_Cd)[idx] = make_float4(BIGF, BIGF, BIGF, BIGF);
    }
    if (idx < NCTA * 32) g_prog[idx] = 0;
}

__global__ void __launch_bounds__(256) norms_k(const float* __restrict__ y,
                                               const float* __restrict__ x2) {
    int w = blockIdx.x * 8 + (threadIdx.x >> 5);
    int lane = threadIdx.x & 31;
    if (w >= 2 * M1) return;
    const float* src = (w < M1) ? (y + (size_t)w * DIM) : (x2 + (size_t)(w - M1) * DIM);
    float4 v = ((const float4*)src)[lane];
    float s = v.x * v.x + v.y * v.y + v.z * v.z + v.w * v.w;
#pragma unroll
    for (int o = 16; o; o >>= 1) s += __shfl_xor_sync(0xffffffffu, s, o);
    if (lane == 0) {
        if (w < M1) g_n1[w] = s; else g_n2[w - M1] = s;
    }
}

// GEMM with diagonal-major scatter epilogue:
// value for (r, c) goes to Cd[r+c+2][r]
__global__ void __launch_bounds__(256) gemm_k(const float* __restrict__ A,
                                              const float* __restrict__ B) {
    __shared__ float As[32][68];
    __shared__ float Bs[32][68];
    const int t  = threadIdx.x;
    const int tx = t & 15, ty = t >> 4;
    const int bi = blockIdx.y << 6, bj = blockIdx.x << 6;
    const int lrow = t >> 2;
    const int lk   = (t & 3) << 3;

    float acc[4][4];
#pragma unroll
    for (int u = 0; u < 4; ++u)
#pragma unroll
        for (int v = 0; v < 4; ++v) acc[u][v] = 0.0f;

    const float* Ap = A + (size_t)(bi + lrow) * DIM + lk;
    const float* Bp = B + (size_t)(bj + lrow) * DIM + lk;

    for (int k0 = 0; k0 < DIM; k0 += 32) {
        float4 a0 = *(const float4*)(Ap + k0);
        float4 a1 = *(const float4*)(Ap + k0 + 4);
        float4 b0 = *(const float4*)(Bp + k0);
        float4 b1 = *(const float4*)(Bp + k0 + 4);
        __syncthreads();
        As[lk + 0][lrow] = a0.x; As[lk + 1][lrow] = a0.y;
        As[lk + 2][lrow] = a0.z; As[lk + 3][lrow] = a0.w;
        As[lk + 4][lrow] = a1.x; As[lk + 5][lrow] = a1.y;
        As[lk + 6][lrow] = a1.z; As[lk + 7][lrow] = a1.w;
        Bs[lk + 0][lrow] = b0.x; Bs[lk + 1][lrow] = b0.y;
        Bs[lk + 2][lrow] = b0.z; Bs[lk + 3][lrow] = b0.w;
        Bs[lk + 4][lrow] = b1.x; Bs[lk + 5][lrow] = b1.y;
        Bs[lk + 6][lrow] = b1.z; Bs[lk + 7][lrow] = b1.w;
        __syncthreads();
#pragma unroll
        for (int kk = 0; kk < 32; ++kk) {
            float4 av = *(const float4*)&As[kk][ty << 2];
            float4 bv = *(const float4*)&Bs[kk][tx << 2];
            float a_[4] = {av.x, av.y, av.z, av.w};
            float b_[4] = {bv.x, bv.y, bv.z, bv.w};
#pragma unroll
            for (int u = 0; u < 4; ++u)
#pragma unroll
                for (int v = 0; v < 4; ++v) acc[u][v] += a_[u] * b_[v];
        }
    }

    float4 nb = *(const float4*)&g_n2[bj + (tx << 2)];
#pragma unroll
    for (int u = 0; u < 4; ++u) {
        int r = bi + (ty << 2) + u;
        float na = g_n1[r];
        float o0 = (na + nb.x - 2.0f * acc[u][0]) * INV_LN2;
        float o1 = (na + nb.y - 2.0f * acc[u][1]) * INV_LN2;
        float o2 = (na + nb.z - 2.0f * acc[u][2]) * INV_LN2;
        float o3 = (na + nb.w - 2.0f * acc[u][3]) * INV_LN2;
        int c = bj + (tx << 2);
        g_Cd[(size_t)(r + c + 2) * CPITCH + r] = o0;
        g_Cd[(size_t)(r + c + 3) * CPITCH + r] = o1;
        g_Cd[(size_t)(r + c + 4) * CPITCH + r] = o2;
        g_Cd[(size_t)(r + c + 5) * CPITCH + r] = o3;
    }
}

// ---------------------------------------------------------------------------
// DP wavefront: 16 single-warp CTAs, 128 rows/CTA, FOUR rows per lane.
// lane L owns rows base+4L+1 .. base+4L+4 (1-based). 273 groups of 8 diags.
__global__ void __launch_bounds__(32, 1) dp_k(float* __restrict__ out) {
    const int cta  = blockIdx.x;
    const int lane = threadIdx.x;
    const int base = cta * 128;
    const bool l0  = (lane == 0);
    const bool l31 = (lane == 31);

    // costs for lane's rows at diag k: float4 at Cd[k][base+4*lane]
    const float* pcost = g_Cd + (size_t)base * CPITCH + base + 4 * lane;

    const float4 BIG4 = make_float4(BIGF, BIGF, BIGF, BIGF);

    const int  wend    = (cta > 0) ? (base + 2048) : -1;  // last real chunk start
    const int  flagmax = wend + 3;
    int*       myflag  = &g_prog[cta * 32];
    const int* pflag   = &g_prog[((cta > 0) ? (cta - 1) : 0) * 32];
    const float* brow  = g_bnd[(cta > 0) ? (cta - 1) : 0];
    int known = -1000000;

    // boundary chunk ring for group g: c0=[g-4..g-1], c1=[g..g+3], c2=[g+4..g+7]
    float4 c0, c1, c2;
    if (cta > 0) {
        int need = base + 15 < flagmax ? base + 15 : flagmax;
        do { known = acq_load(pflag); } while (known < need);
        c0 = ldcg4(brow + base - 4);
        c1 = ldcg4(brow + base);
        c2 = ldcg4(brow + base + 4);
    } else {
        c0 = BIG4; c1 = BIG4; c2 = BIG4;
        c1.x = 0.0f;                       // virtual B[0] = R[0][0] = 0
    }

    float r0 = BIGF, r1 = BIGF, r2 = BIGF, r3 = BIGF;   // rows @ diag k-1
    float u0 = BIGF, u1 = BIGF, u2 = BIGF, u3 = BIGF;   // dg carries
    if (cta == 0 && lane == 0) u0 = 0.0f;  // R[0][0]=0 feeds dg of row 1 at k=2
    float res = BIGF;

    // cost ring: ring[p] = float4 costs for iter (group start + p)
    float4 ring[8];
#pragma unroll
    for (int p = 0; p < 8; ++p)
        ring[p] = __ldg((const float4*)(pcost + (size_t)p * CPITCH));
    const float* pn = pcost + (size_t)8 * CPITCH;

    int g = base;
    float q[8];

#pragma unroll 1
    for (int gi = 0; gi < 273; ++gi, g += 8) {
        // top: acquire in flight; boundary chunks [g+8],[g+12] (published:
        // previous group's end-wait ensured flag >= g+15)
        int fnew = (cta > 0) ? acq_load(pflag) : 0;
        float4 n1 = (g + 8  <= wend) ? ldcg4(brow + g + 8)  : BIG4;
        float4 n2 = (g + 12 <= wend) ? ldcg4(brow + g + 12) : BIG4;

#pragma unroll
        for (int p = 0; p < 8; ++p) {
            float bu = (p == 0) ? c0.w :
                       (p == 1) ? c1.x : (p == 2) ? c1.y :
                       (p == 3) ? c1.z : (p == 4) ? c1.w :
                       (p == 5) ? c2.x : (p == 6) ? c2.y : c2.z;

            float4 cost = ring[p];
            ring[p] = __ldg((const float4*)(pn + (size_t)p * CPITCH));

            float sup = __shfl_up_sync(0xffffffffu, r3, 1);
            float up0 = l0 ? bu : sup;
            // ups for rows 1..3 are same-lane previous values (pre-update)
            float up1 = r0, up2 = r1, up3 = r2;

            float m0 = fminf(fminf(r0, u0), up0);
            float m1 = fminf(fminf(r1, u1), up1);
            float m2 = fminf(fminf(r2, u2), up2);
            float m3 = fminf(fminf(r3, u3), up3);

            float e0 = ex2f(m0 - up0) + ex2f(m0 - r0) + ex2f(m0 - u0);
            float e1 = ex2f(m1 - up1) + ex2f(m1 - r1) + ex2f(m1 - u1);
            float e2 = ex2f(m2 - up2) + ex2f(m2 - r2) + ex2f(m2 - u2);
            float e3 = ex2f(m3 - up3) + ex2f(m3 - r3) + ex2f(m3 - u3);

            float v0 = (cost.x + m0) - lg2f(e0);
            float v1 = (cost.y + m1) - lg2f(e1);
            float v2 = (cost.z + m2) - lg2f(e2);
            float v3 = (cost.w + m3) - lg2f(e3);

            u0 = up0; u1 = up1; u2 = up2; u3 = up3;
            r0 = v0;  r1 = v1;  r2 = v2;  r3 = v3;

            q[p] = r3;
            if (p == 0 && gi == 272) res = r3;   // k = base+2176 (cta15: 4096)
        }

        // publish B[g..g+7] (lane 31's 4th row = base+128), then flag
        if (l31) {
            stcg4(&g_bnd[cta][g],     make_float4(q[0], q[1], q[2], q[3]));
            stcg4(&g_bnd[cta][g + 4], make_float4(q[4], q[5], q[6], q[7]));
            rel_store(myflag, g + 7);
        }

        // end: fold acquire; ensure next top's loads ([g+16],[g+20]) published
        if (cta > 0) {
            if (fnew > known) known = fnew;
            int need = g + 23 < flagmax ? g + 23 : flagmax;
            while (known < need) known = acq_load(pflag);
        }

        c0 = c2; c1 = n1; c2 = n2;
        pn += (size_t)8 * CPITCH;
    }

    if (cta == NCTA - 1 && l31) {
        out[0] = res * LN2F;
    }
}

// ---------------------------------------------------------------------------
extern "C" void kernel_launch(void* const* d_in, const int* in_sizes, int n_in,
                              void* d_out, int out_size) {
    const float* y  = (const float*)d_in[0];
    const float* x2 = (const float*)d_in[1];
    float* out = (float*)d_out;

    const int n4 = (CROWS * CPITCH) / 4;
    initc_k<<<(n4 + 1023) / 1024, 1024>>>();
    norms_k<<<512, 256>>>(y, x2);
    gemm_k<<<dim3(M2 / 64, M1 / 64), 256>>>(y, x2);
    dp_k<<<NCTA, 32>>>(out);
}

// round 11
// speedup vs baseline: 1.1524x; 1.0396x over previous
#include <cuda_runtime.h>
#include <cuda_bf16.h>
#include <cstdint>

// ---------------------------------------------------------------------------
// GMDTW (soft-DTW, gamma=1), m1=m2=2048, d=128. log2-domain DP.
// R11: R8 layout (32 CTAs x 64 rows, 2 rows/lane) with a hand-scheduled inner
// body: batched MUFUs, carried pre-mins, early shfl, and acquires folded only
// every other group. Goal: collapse the ~300cyc fixed per-diagonal cost.
// ---------------------------------------------------------------------------

#define M1 2048
#define M2 2048
#define DIM 128
#define NCTA 32
#define CPITCH 2080          // floats per diagonal row of Cd
#define CROWS  4120          // diagonal rows (k) incl. prefetch overrun pad
#define BIGF 1e30f
#define INV_LN2 1.44269504088896340736f
#define LN2F    0.69314718055994530942f

__device__ float g_Cd[(size_t)CROWS * CPITCH];  // Cd[k][r] = C[r][k-r-2]*INV_LN2
__device__ float g_n1[M1];
__device__ float g_n2[M2];
__device__ float g_bnd[NCTA][4240];             // g_bnd[w][k] = R~[row 64(w+1)] @ diag k
__device__ int   g_prog[NCTA * 32];             // flag per 128B

__device__ __forceinline__ float ex2f(float x) {
    float r; asm("ex2.approx.f32 %0, %1;" : "=f"(r) : "f"(x)); return r;
}
__device__ __forceinline__ float lg2f(float x) {
    float r; asm("lg2.approx.f32 %0, %1;" : "=f"(r) : "f"(x)); return r;
}
__device__ __forceinline__ int acq_load(const int* p) {
    int v; asm volatile("ld.global.acquire.gpu.b32 %0, [%1];" : "=r"(v) : "l"(p) : "memory");
    return v;
}
__device__ __forceinline__ void rel_store(int* p, int v) {
    asm volatile("st.global.release.gpu.b32 [%0], %1;" :: "l"(p), "r"(v) : "memory");
}
__device__ __forceinline__ float4 ldcg4(const float* p) {
    float4 v;
    asm volatile("ld.global.cg.v4.f32 {%0,%1,%2,%3}, [%4];"
                 : "=f"(v.x), "=f"(v.y), "=f"(v.z), "=f"(v.w) : "l"(p) : "memory");
    return v;
}
__device__ __forceinline__ void stcg4(float* p, float4 v) {
    asm volatile("st.global.cg.v4.f32 [%0], {%1,%2,%3,%4};"
                 :: "l"(p), "f"(v.x), "f"(v.y), "f"(v.z), "f"(v.w) : "memory");
}

// ---------------------------------------------------------------------------
__global__ void __launch_bounds__(1024) initc_k() {
    size_t idx = (size_t)blockIdx.x * 1024 + threadIdx.x;
    const size_t n4 = (size_t)CROWS * CPITCH / 4;
    if (idx < n4) {
        ((float4*)g_Cd)[idx] = make_float4(BIGF, BIGF, BIGF, BIGF);
    }
    if (idx < NCTA * 32) g_prog[idx] = 0;
}

__global__ void __launch_bounds__(256) norms_k(const float* __restrict__ y,
                                               const float* __restrict__ x2) {
    int w = blockIdx.x * 8 + (threadIdx.x >> 5);
    int lane = threadIdx.x & 31;
    if (w >= 2 * M1) return;
    const float* src = (w < M1) ? (y + (size_t)w * DIM) : (x2 + (size_t)(w - M1) * DIM);
    float4 v = ((const float4*)src)[lane];
    float s = v.x * v.x + v.y * v.y + v.z * v.z + v.w * v.w;
#pragma unroll
    for (int o = 16; o; o >>= 1) s += __shfl_xor_sync(0xffffffffu, s, o);
    if (lane == 0) {
        if (w < M1) g_n1[w] = s; else g_n2[w - M1] = s;
    }
}

// GEMM with diagonal-major scatter epilogue: (r,c) -> Cd[r+c+2][r]
__global__ void __launch_bounds__(256) gemm_k(const float* __restrict__ A,
                                              const float* __restrict__ B) {
    __shared__ float As[32][68];
    __shared__ float Bs[32][68];
    const int t  = threadIdx.x;
    const int tx = t & 15, ty = t >> 4;
    const int bi = blockIdx.y << 6, bj = blockIdx.x << 6;
    const int lrow = t >> 2;
    const int lk   = (t & 3) << 3;

    float acc[4][4];
#pragma unroll
    for (int u = 0; u < 4; ++u)
#pragma unroll
        for (int v = 0; v < 4; ++v) acc[u][v] = 0.0f;

    const float* Ap = A + (size_t)(bi + lrow) * DIM + lk;
    const float* Bp = B + (size_t)(bj + lrow) * DIM + lk;

    for (int k0 = 0; k0 < DIM; k0 += 32) {
        float4 a0 = *(const float4*)(Ap + k0);
        float4 a1 = *(const float4*)(Ap + k0 + 4);
        float4 b0 = *(const float4*)(Bp + k0);
        float4 b1 = *(const float4*)(Bp + k0 + 4);
        __syncthreads();
        As[lk + 0][lrow] = a0.x; As[lk + 1][lrow] = a0.y;
        As[lk + 2][lrow] = a0.z; As[lk + 3][lrow] = a0.w;
        As[lk + 4][lrow] = a1.x; As[lk + 5][lrow] = a1.y;
        As[lk + 6][lrow] = a1.z; As[lk + 7][lrow] = a1.w;
        Bs[lk + 0][lrow] = b0.x; Bs[lk + 1][lrow] = b0.y;
        Bs[lk + 2][lrow] = b0.z; Bs[lk + 3][lrow] = b0.w;
        Bs[lk + 4][lrow] = b1.x; Bs[lk + 5][lrow] = b1.y;
        Bs[lk + 6][lrow] = b1.z; Bs[lk + 7][lrow] = b1.w;
        __syncthreads();
#pragma unroll
        for (int kk = 0; kk < 32; ++kk) {
            float4 av = *(const float4*)&As[kk][ty << 2];
            float4 bv = *(const float4*)&Bs[kk][tx << 2];
            float a_[4] = {av.x, av.y, av.z, av.w};
            float b_[4] = {bv.x, bv.y, bv.z, bv.w};
#pragma unroll
            for (int u = 0; u < 4; ++u)
#pragma unroll
                for (int v = 0; v < 4; ++v) acc[u][v] += a_[u] * b_[v];
        }
    }

    float4 nb = *(const float4*)&g_n2[bj + (tx << 2)];
#pragma unroll
    for (int u = 0; u < 4; ++u) {
        int r = bi + (ty << 2) + u;
        float na = g_n1[r];
        float o0 = (na + nb.x - 2.0f * acc[u][0]) * INV_LN2;
        float o1 = (na + nb.y - 2.0f * acc[u][1]) * INV_LN2;
        float o2 = (na + nb.z - 2.0f * acc[u][2]) * INV_LN2;
        float o3 = (na + nb.w - 2.0f * acc[u][3]) * INV_LN2;
        int c = bj + (tx << 2);
        g_Cd[(size_t)(r + c + 2) * CPITCH + r] = o0;
        g_Cd[(size_t)(r + c + 3) * CPITCH + r] = o1;
        g_Cd[(size_t)(r + c + 4) * CPITCH + r] = o2;
        g_Cd[(size_t)(r + c + 5) * CPITCH + r] = o3;
    }
}

// ---------------------------------------------------------------------------
// DP wavefront: 32 single-warp CTAs, 64 rows/CTA, 2 rows/lane, hand-scheduled.
__global__ void __launch_bounds__(32, 1) dp_k(float* __restrict__ out) {
    const int cta  = blockIdx.x;
    const int lane = threadIdx.x;
    const int base = cta * 64;
    const bool l0  = (lane == 0);
    const bool l31 = (lane == 31);

    // lane L: rows iA = base+2L+1, iB = base+2L+2; costs float2 @ Cd[k][base+2L]
    const float* pcost = g_Cd + (size_t)base * CPITCH + base + 2 * lane;

    const float4 BIG4 = make_float4(BIGF, BIGF, BIGF, BIGF);

    const int  wend    = (cta > 0) ? (base + 2048) : -1;
    const int  flagmax = wend + 3;
    int*       myflag  = &g_prog[cta * 32];
    const int* pflag   = &g_prog[((cta > 0) ? (cta - 1) : 0) * 32];
    const float* brow  = g_bnd[(cta > 0) ? (cta - 1) : 0];
    int known = -1000000;

    // boundary chunk ring for group g: c0=[g-4..g-1], c1=[g..g+3], c2=[g+4..g+7]
    float4 c0, c1, c2;
    if (cta > 0) {
        // initial wait covers group tops gi=0 (g+15=base+15) and gi=1 (base+23)
        int need = base + 23 < flagmax ? base + 23 : flagmax;
        do { known = acq_load(pflag); } while (known < need);
        c0 = ldcg4(brow + base - 4);
        c1 = ldcg4(brow + base);
        c2 = ldcg4(brow + base + 4);
    } else {
        c0 = BIG4; c1 = BIG4; c2 = BIG4;
        c1.x = 0.0f;                       // virtual B[0] = R[0][0] = 0
    }

    float rA1 = BIGF, rB1 = BIGF;          // rows @ diag k-1
    float uA  = BIGF, uB  = BIGF;          // dg carries
    float pmA = BIGF, pmB = BIGF;          // fmin(r, u) carried from prev position
    float sh  = BIGF;                      // shfl of rB1, issued end of prev position
    float res = BIGF;

    // cost ring
    float2 ring[8];
#pragma unroll
    for (int p = 0; p < 8; ++p)
        ring[p] = *(const float2*)(pcost + (size_t)p * CPITCH);
    const float* pn = pcost + (size_t)8 * CPITCH;

    int g = base;
    int fnew = 0;
    float q[8];

#pragma unroll 1
    for (int gi = 0; gi < 265; ++gi, g += 8) {
        // boundary chunks for next group (gated: checks ensured flag coverage)
        float4 n1 = (g + 8  <= wend) ? ldcg4(brow + g + 8)  : BIG4;
        float4 n2 = (g + 12 <= wend) ? ldcg4(brow + g + 12) : BIG4;
        // acquire issued on EVEN groups only (folded at end of odd groups)
        if (((gi & 1) == 0) && cta > 0) fnew = acq_load(pflag);

#pragma unroll
        for (int p = 0; p < 8; ++p) {
            float bu = (p == 0) ? c0.w :
                       (p == 1) ? c1.x : (p == 2) ? c1.y :
                       (p == 3) ? c1.z : (p == 4) ? c1.w :
                       (p == 5) ? c2.x : (p == 6) ? c2.y : c2.z;

            float2 cost = ring[p];

            float upA = l0 ? bu : sh;
            float upB = rA1;                    // pre-update
            float mA  = fminf(pmA, upA);
            float mB  = fminf(pmB, upB);

            // batched MUFUs: producers far from consumers
            float xA0 = ex2f(mA - upA);
            float xA1 = ex2f(mA - rA1);
            float xA2 = ex2f(mA - uA);
            float xB0 = ex2f(mB - upB);
            float xB1 = ex2f(mB - rB1);
            float xB2 = ex2f(mB - uB);
            float eA  = (xA0 + xA1) + xA2;
            float eB  = (xB0 + xB1) + xB2;
            float tA  = lg2f(eA);
            float tB  = lg2f(eB);

            uA  = upA; uB = upB;
            rA1 = (cost.x + mA) - tA;
            rB1 = (cost.y + mB) - tB;

            sh  = __shfl_up_sync(0xffffffffu, rB1, 1);   // issue ASAP for next p
            pmA = fminf(rA1, uA);
            pmB = fminf(rB1, uB);

            q[p] = rB1;
            if (p == 0 && gi == 264) res = rB1;   // k = base+2112 (cta31: 4096)

            ring[p] = *(const float2*)(pn + (size_t)p * CPITCH);  // refill (k+8)
        }

        // publish B[g..g+7] (lane 31's row = base+64), then flag
        if (l31) {
            stcg4(&g_bnd[cta][g],     make_float4(q[0], q[1], q[2], q[3]));
            stcg4(&g_bnd[cta][g + 4], make_float4(q[4], q[5], q[6], q[7]));
            rel_store(myflag, g + 7);
        }

        // fold + enforce on ODD groups: covers tops of the next two groups
        // (loads [g+16],[g+20] need flag g+23; [g+24],[g+28] need g+31)
        if (((gi & 1) == 1) && cta > 0) {
            if (fnew > known) known = fnew;
            int need = g + 31 < flagmax ? g + 31 : flagmax;
            while (known < need) known = acq_load(pflag);
        }

        c0 = c2; c1 = n1; c2 = n2;
        pn += (size_t)8 * CPITCH;
    }

    if (cta == NCTA - 1 && l31) {
        out[0] = res * LN2F;
    }
}

// ---------------------------------------------------------------------------
extern "C" void kernel_launch(void* const* d_in, const int* in_sizes, int n_in,
                              void* d_out, int out_size) {
    const float* y  = (const float*)d_in[0];
    const float* x2 = (const float*)d_in[1];
    float* out = (float*)d_out;

    const int n4 = (CROWS * CPITCH) / 4;
    initc_k<<<(n4 + 1023) / 1024, 1024>>>();
    norms_k<<<512, 256>>>(y, x2);
    gemm_k<<<dim3(M2 / 64, M1 / 64), 256>>>(y, x2);
    dp_k<<<NCTA, 32>>>(out);
}

// round 12
// speedup vs baseline: 1.1566x; 1.0036x over previous
#include <cuda_runtime.h>
#include <cuda_bf16.h>
#include <cstdint>

// ---------------------------------------------------------------------------
// GMDTW (soft-DTW, gamma=1), m1=m2=2048, d=128. log2-domain DP.
// R12: costs staged through SMEM (LDG two groups ahead -> STS one group
// ahead -> LDS in-loop). Kills the per-iteration L2-latency exposure that
// R8-R11 evidence isolated. Layout/protocol otherwise identical to R11.
// ---------------------------------------------------------------------------

#define M1 2048
#define M2 2048
#define DIM 128
#define NCTA 32
#define CPITCH 2080          // floats per diagonal row of Cd
#define CROWS  4120          // diagonal rows (k) incl. prefetch overrun pad
#define BIGF 1e30f
#define INV_LN2 1.44269504088896340736f
#define LN2F    0.69314718055994530942f

__device__ float g_Cd[(size_t)CROWS * CPITCH];  // Cd[k][r] = C[r][k-r-2]*INV_LN2
__device__ float g_n1[M1];
__device__ float g_n2[M2];
__device__ float g_bnd[NCTA][4240];             // g_bnd[w][k] = R~[row 64(w+1)] @ diag k
__device__ int   g_prog[NCTA * 32];             // flag per 128B

__device__ __forceinline__ float ex2f(float x) {
    float r; asm("ex2.approx.f32 %0, %1;" : "=f"(r) : "f"(x)); return r;
}
__device__ __forceinline__ float lg2f(float x) {
    float r; asm("lg2.approx.f32 %0, %1;" : "=f"(r) : "f"(x)); return r;
}
__device__ __forceinline__ int acq_load(const int* p) {
    int v; asm volatile("ld.global.acquire.gpu.b32 %0, [%1];" : "=r"(v) : "l"(p) : "memory");
    return v;
}
__device__ __forceinline__ void rel_store(int* p, int v) {
    asm volatile("st.global.release.gpu.b32 [%0], %1;" :: "l"(p), "r"(v) : "memory");
}
__device__ __forceinline__ float4 ldcg4(const float* p) {
    float4 v;
    asm volatile("ld.global.cg.v4.f32 {%0,%1,%2,%3}, [%4];"
                 : "=f"(v.x), "=f"(v.y), "=f"(v.z), "=f"(v.w) : "l"(p) : "memory");
    return v;
}
__device__ __forceinline__ void stcg4(float* p, float4 v) {
    asm volatile("st.global.cg.v4.f32 [%0], {%1,%2,%3,%4};"
                 :: "l"(p), "f"(v.x), "f"(v.y), "f"(v.z), "f"(v.w) : "memory");
}

// ---------------------------------------------------------------------------
__global__ void __launch_bounds__(1024) initc_k() {
    size_t idx = (size_t)blockIdx.x * 1024 + threadIdx.x;
    const size_t n4 = (size_t)CROWS * CPITCH / 4;
    if (idx < n4) {
        ((float4*)g_Cd)[idx] = make_float4(BIGF, BIGF, BIGF, BIGF);
    }
    if (idx < NCTA * 32) g_prog[idx] = 0;
}

__global__ void __launch_bounds__(256) norms_k(const float* __restrict__ y,
                                               const float* __restrict__ x2) {
    int w = blockIdx.x * 8 + (threadIdx.x >> 5);
    int lane = threadIdx.x & 31;
    if (w >= 2 * M1) return;
    const float* src = (w < M1) ? (y + (size_t)w * DIM) : (x2 + (size_t)(w - M1) * DIM);
    float4 v = ((const float4*)src)[lane];
    float s = v.x * v.x + v.y * v.y + v.z * v.z + v.w * v.w;
#pragma unroll
    for (int o = 16; o; o >>= 1) s += __shfl_xor_sync(0xffffffffu, s, o);
    if (lane == 0) {
        if (w < M1) g_n1[w] = s; else g_n2[w - M1] = s;
    }
}

// GEMM with diagonal-major scatter epilogue: (r,c) -> Cd[r+c+2][r]
__global__ void __launch_bounds__(256) gemm_k(const float* __restrict__ A,
                                              const float* __restrict__ B) {
    __shared__ float As[32][68];
    __shared__ float Bs[32][68];
    const int t  = threadIdx.x;
    const int tx = t & 15, ty = t >> 4;
    const int bi = blockIdx.y << 6, bj = blockIdx.x << 6;
    const int lrow = t >> 2;
    const int lk   = (t & 3) << 3;

    float acc[4][4];
#pragma unroll
    for (int u = 0; u < 4; ++u)
#pragma unroll
        for (int v = 0; v < 4; ++v) acc[u][v] = 0.0f;

    const float* Ap = A + (size_t)(bi + lrow) * DIM + lk;
    const float* Bp = B + (size_t)(bj + lrow) * DIM + lk;

    for (int k0 = 0; k0 < DIM; k0 += 32) {
        float4 a0 = *(const float4*)(Ap + k0);
        float4 a1 = *(const float4*)(Ap + k0 + 4);
        float4 b0 = *(const float4*)(Bp + k0);
        float4 b1 = *(const float4*)(Bp + k0 + 4);
        __syncthreads();
        As[lk + 0][lrow] = a0.x; As[lk + 1][lrow] = a0.y;
        As[lk + 2][lrow] = a0.z; As[lk + 3][lrow] = a0.w;
        As[lk + 4][lrow] = a1.x; As[lk + 5][lrow] = a1.y;
        As[lk + 6][lrow] = a1.z; As[lk + 7][lrow] = a1.w;
        Bs[lk + 0][lrow] = b0.x; Bs[lk + 1][lrow] = b0.y;
        Bs[lk + 2][lrow] = b0.z; Bs[lk + 3][lrow] = b0.w;
        Bs[lk + 4][lrow] = b1.x; Bs[lk + 5][lrow] = b1.y;
        Bs[lk + 6][lrow] = b1.z; Bs[lk + 7][lrow] = b1.w;
        __syncthreads();
#pragma unroll
        for (int kk = 0; kk < 32; ++kk) {
            float4 av = *(const float4*)&As[kk][ty << 2];
            float4 bv = *(const float4*)&Bs[kk][tx << 2];
            float a_[4] = {av.x, av.y, av.z, av.w};
            float b_[4] = {bv.x, bv.y, bv.z, bv.w};
#pragma unroll
            for (int u = 0; u < 4; ++u)
#pragma unroll
                for (int v = 0; v < 4; ++v) acc[u][v] += a_[u] * b_[v];
        }
    }

    float4 nb = *(const float4*)&g_n2[bj + (tx << 2)];
#pragma unroll
    for (int u = 0; u < 4; ++u) {
        int r = bi + (ty << 2) + u;
        float na = g_n1[r];
        float o0 = (na + nb.x - 2.0f * acc[u][0]) * INV_LN2;
        float o1 = (na + nb.y - 2.0f * acc[u][1]) * INV_LN2;
        float o2 = (na + nb.z - 2.0f * acc[u][2]) * INV_LN2;
        float o3 = (na + nb.w - 2.0f * acc[u][3]) * INV_LN2;
        int c = bj + (tx << 2);
        g_Cd[(size_t)(r + c + 2) * CPITCH + r] = o0;
        g_Cd[(size_t)(r + c + 3) * CPITCH + r] = o1;
        g_Cd[(size_t)(r + c + 4) * CPITCH + r] = o2;
        g_Cd[(size_t)(r + c + 5) * CPITCH + r] = o3;
    }
}

// ---------------------------------------------------------------------------
// DP wavefront: 32 single-warp CTAs, 64 rows/CTA, 2 rows/lane.
// Costs staged: LDG (group gi, for gi+2) -> STS (top of gi+1) -> LDS (gi+2).
__global__ void __launch_bounds__(32, 1) dp_k(float* __restrict__ out) {
    const int cta  = blockIdx.x;
    const int lane = threadIdx.x;
    const int base = cta * 64;
    const bool l0  = (lane == 0);
    const bool l31 = (lane == 31);

    // smem cost buffers: 2 x 8 positions x 64 floats
    __shared__ __align__(16) float cbuf[2][8][64];

    const float4 BIG4 = make_float4(BIGF, BIGF, BIGF, BIGF);

    const int  wend    = (cta > 0) ? (base + 2048) : -1;
    const int  flagmax = wend + 3;
    int*       myflag  = &g_prog[cta * 32];
    const int* pflag   = &g_prog[((cta > 0) ? (cta - 1) : 0) * 32];
    const float* brow  = g_bnd[(cta > 0) ? (cta - 1) : 0];
    int known = -1000000;

    // cooperative cost-staging indices: j-th load (j=0..3): idx = j*32+lane,
    // position p = idx>>4 (0..7), q = idx&15 (float4 within row)
    const int sp[4] = { (0 * 32 + lane) >> 4, (1 * 32 + lane) >> 4,
                        (2 * 32 + lane) >> 4, (3 * 32 + lane) >> 4 };
    const int sq = (lane & 15) << 2;       // float index within row (same all j)
    // gmem source for position p at group-start G: Cd[G+p][base+sq..sq+3]
    const float* csrc = g_Cd + (size_t)base * CPITCH + base + sq;

    // prefill: buf0 = group 0 (rows base+0..7), buf1 = group 1 (rows +8..15)
#pragma unroll
    for (int j = 0; j < 4; ++j) {
        *(float4*)&cbuf[0][sp[j]][sq] =
            __ldg((const float4*)(csrc + (size_t)(sp[j]) * CPITCH));
        *(float4*)&cbuf[1][sp[j]][sq] =
            __ldg((const float4*)(csrc + (size_t)(8 + sp[j]) * CPITCH));
    }
    // in-flight regs for group 2 (rows +16..23)
    float4 rldg[4];
#pragma unroll
    for (int j = 0; j < 4; ++j)
        rldg[j] = __ldg((const float4*)(csrc + (size_t)(16 + sp[j]) * CPITCH));
    __syncwarp();

    // boundary chunk ring: c0=[g-4..g-1], c1=[g..g+3], c2=[g+4..g+7]
    float4 c0, c1, c2;
    if (cta > 0) {
        int need = base + 23 < flagmax ? base + 23 : flagmax;
        do { known = acq_load(pflag); } while (known < need);
        c0 = ldcg4(brow + base - 4);
        c1 = ldcg4(brow + base);
        c2 = ldcg4(brow + base + 4);
    } else {
        c0 = BIG4; c1 = BIG4; c2 = BIG4;
        c1.x = 0.0f;                       // virtual B[0] = R[0][0] = 0
    }

    float rA1 = BIGF, rB1 = BIGF;          // rows @ diag k-1
    float uA  = BIGF, uB  = BIGF;          // dg carries
    float pmA = BIGF, pmB = BIGF;          // fmin(r,u) carried
    float sh  = BIGF;                      // shfl of rB1 from prev position
    float res = BIGF;

    const int ll2 = 2 * lane;              // smem column for this lane's rows
    int g = base;
    int fnew = 0;
    float q[8];

#pragma unroll 1
    for (int gi = 0; gi < 265; ++gi, g += 8) {
        const int cb = gi & 1;             // buffer consumed this group
        // ---- group top ----
        // STS: regs (loaded last group) -> buffer for group gi+1
        #pragma unroll
        for (int j = 0; j < 4; ++j)
            *(float4*)&cbuf[cb ^ 1][sp[j]][sq] = rldg[j];
        // LDG: rows for group gi+2 (consumed 2 groups from now)
        #pragma unroll
        for (int j = 0; j < 4; ++j)
            rldg[j] = __ldg((const float4*)(csrc +
                          (size_t)(8 * gi + 16 + sp[j]) * CPITCH));
        // boundary chunks for next group
        float4 n1 = (g + 8  <= wend) ? ldcg4(brow + g + 8)  : BIG4;
        float4 n2 = (g + 12 <= wend) ? ldcg4(brow + g + 12) : BIG4;
        // acquire on even groups
        if (((gi & 1) == 0) && cta > 0) fnew = acq_load(pflag);

        // cost prefetch for position 0 (LDS, one position ahead)
        float2 cnext = *(const float2*)&cbuf[cb][0][ll2];

#pragma unroll
        for (int p = 0; p < 8; ++p) {
            float bu = (p == 0) ? c0.w :
                       (p == 1) ? c1.x : (p == 2) ? c1.y :
                       (p == 3) ? c1.z : (p == 4) ? c1.w :
                       (p == 5) ? c2.x : (p == 6) ? c2.y : c2.z;

            float2 cost = cnext;
            if (p < 7) cnext = *(const float2*)&cbuf[cb][p + 1][ll2];

            float upA = l0 ? bu : sh;
            float upB = rA1;                    // pre-update
            float mA  = fminf(pmA, upA);
            float mB  = fminf(pmB, upB);

            float xA0 = ex2f(mA - upA);
            float xA1 = ex2f(mA - rA1);
            float xA2 = ex2f(mA - uA);
            float xB0 = ex2f(mB - upB);
            float xB1 = ex2f(mB - rB1);
            float xB2 = ex2f(mB - uB);
            float eA  = (xA0 + xA1) + xA2;
            float eB  = (xB0 + xB1) + xB2;
            float tA  = lg2f(eA);
            float tB  = lg2f(eB);

            uA  = upA; uB = upB;
            rA1 = (cost.x + mA) - tA;
            rB1 = (cost.y + mB) - tB;

            sh  = __shfl_up_sync(0xffffffffu, rB1, 1);
            pmA = fminf(rA1, uA);
            pmB = fminf(rB1, uB);

            q[p] = rB1;
            if (p == 0 && gi == 264) res = rB1;   // k = base+2112 (cta31: 4096)
        }

        // publish B[g..g+7], then flag
        if (l31) {
            stcg4(&g_bnd[cta][g],     make_float4(q[0], q[1], q[2], q[3]));
            stcg4(&g_bnd[cta][g + 4], make_float4(q[4], q[5], q[6], q[7]));
            rel_store(myflag, g + 7);
        }

        // fold + enforce on odd groups (covers next two group tops)
        if (((gi & 1) == 1) && cta > 0) {
            if (fnew > known) known = fnew;
            int need = g + 31 < flagmax ? g + 31 : flagmax;
            while (known < need) known = acq_load(pflag);
        }

        c0 = c2; c1 = n1; c2 = n2;
        __syncwarp();                      // order LDS (this group) vs STS (next top)
    }

    if (cta == NCTA - 1 && l31) {
        out[0] = res * LN2F;
    }
}

// ---------------------------------------------------------------------------
extern "C" void kernel_launch(void* const* d_in, const int* in_sizes, int n_in,
                              void* d_out, int out_size) {
    const float* y  = (const float*)d_in[0];
    const float* x2 = (const float*)d_in[1];
    float* out = (float*)d_out;

    const int n4 = (CROWS * CPITCH) / 4;
    initc_k<<<(n4 + 1023) / 1024, 1024>>>();
    norms_k<<<512, 256>>>(y, x2);
    gemm_k<<<dim3(M2 / 64, M1 / 64), 256>>>(y, x2);
    dp_k<<<NCTA, 32>>>(out);
}

// round 13
// speedup vs baseline: 1.4306x; 1.2370x over previous
#include <cuda_runtime.h>
#include <cuda_bf16.h>
#include <cstdint>

// ---------------------------------------------------------------------------
// GMDTW (soft-DTW, gamma=1), m1=m2=2048, d=128. log2-domain DP.
// R13: fixes R12 staging off-by-one (group gi=1 consumed group-2 costs);
// 16-diag groups (halve group overhead); ex2(0)=1 identity (6 MUFU/iter);
// lean unrolled body. Protocol: proven release/acquire flags.
// ---------------------------------------------------------------------------

#define M1 2048
#define M2 2048
#define DIM 128
#define NCTA 32
#define CPITCH 2080          // floats per diagonal row of Cd
#define CROWS  4176          // diagonal rows incl. staging overrun pad
#define BIGF 1e30f
#define INV_LN2 1.44269504088896340736f
#define LN2F    0.69314718055994530942f

__device__ float g_Cd[(size_t)CROWS * CPITCH];  // Cd[k][r] = C[r][k-r-2]*INV_LN2
__device__ float g_n1[M1];
__device__ float g_n2[M2];
__device__ float g_bnd[NCTA][4240];             // g_bnd[w][k] = R~[row 64(w+1)] @ diag k
__device__ int   g_prog[NCTA * 32];             // flag per 128B

__device__ __forceinline__ float ex2f(float x) {
    float r; asm("ex2.approx.f32 %0, %1;" : "=f"(r) : "f"(x)); return r;
}
__device__ __forceinline__ float lg2f(float x) {
    float r; asm("lg2.approx.f32 %0, %1;" : "=f"(r) : "f"(x)); return r;
}
__device__ __forceinline__ int acq_load(const int* p) {
    int v; asm volatile("ld.global.acquire.gpu.b32 %0, [%1];" : "=r"(v) : "l"(p) : "memory");
    return v;
}
__device__ __forceinline__ void rel_store(int* p, int v) {
    asm volatile("st.global.release.gpu.b32 [%0], %1;" :: "l"(p), "r"(v) : "memory");
}
__device__ __forceinline__ float4 ldcg4(const float* p) {
    float4 v;
    asm volatile("ld.global.cg.v4.f32 {%0,%1,%2,%3}, [%4];"
                 : "=f"(v.x), "=f"(v.y), "=f"(v.z), "=f"(v.w) : "l"(p) : "memory");
    return v;
}
__device__ __forceinline__ void stcg4(float* p, float4 v) {
    asm volatile("st.global.cg.v4.f32 [%0], {%1,%2,%3,%4};"
                 :: "l"(p), "f"(v.x), "f"(v.y), "f"(v.z), "f"(v.w) : "memory");
}

// ---------------------------------------------------------------------------
__global__ void __launch_bounds__(1024) initc_k() {
    size_t idx = (size_t)blockIdx.x * 1024 + threadIdx.x;
    const size_t n4 = (size_t)CROWS * CPITCH / 4;
    if (idx < n4) {
        ((float4*)g_Cd)[idx] = make_float4(BIGF, BIGF, BIGF, BIGF);
    }
    if (idx < NCTA * 32) g_prog[idx] = 0;
}

__global__ void __launch_bounds__(256) norms_k(const float* __restrict__ y,
                                               const float* __restrict__ x2) {
    int w = blockIdx.x * 8 + (threadIdx.x >> 5);
    int lane = threadIdx.x & 31;
    if (w >= 2 * M1) return;
    const float* src = (w < M1) ? (y + (size_t)w * DIM) : (x2 + (size_t)(w - M1) * DIM);
    float4 v = ((const float4*)src)[lane];
    float s = v.x * v.x + v.y * v.y + v.z * v.z + v.w * v.w;
#pragma unroll
    for (int o = 16; o; o >>= 1) s += __shfl_xor_sync(0xffffffffu, s, o);
    if (lane == 0) {
        if (w < M1) g_n1[w] = s; else g_n2[w - M1] = s;
    }
}

// GEMM with diagonal-major scatter epilogue: (r,c) -> Cd[r+c+2][r]
__global__ void __launch_bounds__(256) gemm_k(const float* __restrict__ A,
                                              const float* __restrict__ B) {
    __shared__ float As[32][68];
    __shared__ float Bs[32][68];
    const int t  = threadIdx.x;
    const int tx = t & 15, ty = t >> 4;
    const int bi = blockIdx.y << 6, bj = blockIdx.x << 6;
    const int lrow = t >> 2;
    const int lk   = (t & 3) << 3;

    float acc[4][4];
#pragma unroll
    for (int u = 0; u < 4; ++u)
#pragma unroll
        for (int v = 0; v < 4; ++v) acc[u][v] = 0.0f;

    const float* Ap = A + (size_t)(bi + lrow) * DIM + lk;
    const float* Bp = B + (size_t)(bj + lrow) * DIM + lk;

    for (int k0 = 0; k0 < DIM; k0 += 32) {
        float4 a0 = *(const float4*)(Ap + k0);
        float4 a1 = *(const float4*)(Ap + k0 + 4);
        float4 b0 = *(const float4*)(Bp + k0);
        float4 b1 = *(const float4*)(Bp + k0 + 4);
        __syncthreads();
        As[lk + 0][lrow] = a0.x; As[lk + 1][lrow] = a0.y;
        As[lk + 2][lrow] = a0.z; As[lk + 3][lrow] = a0.w;
        As[lk + 4][lrow] = a1.x; As[lk + 5][lrow] = a1.y;
        As[lk + 6][lrow] = a1.z; As[lk + 7][lrow] = a1.w;
        Bs[lk + 0][lrow] = b0.x; Bs[lk + 1][lrow] = b0.y;
        Bs[lk + 2][lrow] = b0.z; Bs[lk + 3][lrow] = b0.w;
        Bs[lk + 4][lrow] = b1.x; Bs[lk + 5][lrow] = b1.y;
        Bs[lk + 6][lrow] = b1.z; Bs[lk + 7][lrow] = b1.w;
        __syncthreads();
#pragma unroll
        for (int kk = 0; kk < 32; ++kk) {
            float4 av = *(const float4*)&As[kk][ty << 2];
            float4 bv = *(const float4*)&Bs[kk][tx << 2];
            float a_[4] = {av.x, av.y, av.z, av.w};
            float b_[4] = {bv.x, bv.y, bv.z, bv.w};
#pragma unroll
            for (int u = 0; u < 4; ++u)
#pragma unroll
                for (int v = 0; v < 4; ++v) acc[u][v] += a_[u] * b_[v];
        }
    }

    float4 nb = *(const float4*)&g_n2[bj + (tx << 2)];
#pragma unroll
    for (int u = 0; u < 4; ++u) {
        int r = bi + (ty << 2) + u;
        float na = g_n1[r];
        float o0 = (na + nb.x - 2.0f * acc[u][0]) * INV_LN2;
        float o1 = (na + nb.y - 2.0f * acc[u][1]) * INV_LN2;
        float o2 = (na + nb.z - 2.0f * acc[u][2]) * INV_LN2;
        float o3 = (na + nb.w - 2.0f * acc[u][3]) * INV_LN2;
        int c = bj + (tx << 2);
        g_Cd[(size_t)(r + c + 2) * CPITCH + r] = o0;
        g_Cd[(size_t)(r + c + 3) * CPITCH + r] = o1;
        g_Cd[(size_t)(r + c + 4) * CPITCH + r] = o2;
        g_Cd[(size_t)(r + c + 5) * CPITCH + r] = o3;
    }
}

// ---------------------------------------------------------------------------
// DP wavefront: 32 single-warp CTAs, 64 rows/CTA, 2 rows/lane, 16-diag groups.
// Cost staging: LDG (top of gi, for group gi+2) -> STS (top of gi+1)
//               -> LDS (consumed in gi+2). 133 groups.
__global__ void __launch_bounds__(32, 1) dp_k(float* __restrict__ out) {
    const int cta  = blockIdx.x;
    const int lane = threadIdx.x;
    const int base = cta * 64;
    const bool l0  = (lane == 0);
    const bool l31 = (lane == 31);

    __shared__ __align__(16) float cbuf[2][16][64];   // 8 KB

    const float4 BIG4 = make_float4(BIGF, BIGF, BIGF, BIGF);

    const int  wend    = (cta > 0) ? (base + 2048) : -1;
    const int  flagmax = wend + 3;
    int*       myflag  = &g_prog[cta * 32];
    const int* pflag   = &g_prog[((cta > 0) ? (cta - 1) : 0) * 32];
    const float* brow  = g_bnd[(cta > 0) ? (cta - 1) : 0];
    int known = -1000000;

    // staging geometry: j-th transfer (j=0..7) handles position p=2j+ph,
    // float4 at column qf, where ph = lane>>4, qf = (lane&15)*4.
    const int ph = lane >> 4;
    const int qf = (lane & 15) << 2;
    const float* cldg = g_Cd + (size_t)base * CPITCH + base + qf;

    // prefill: cbuf[0] <- group 0 (diag rows base+0..15)
#pragma unroll
    for (int j = 0; j < 8; ++j) {
        float4 v = __ldg((const float4*)(cldg + (size_t)(2 * j + ph) * CPITCH));
        *(float4*)&cbuf[0][2 * j + ph][qf] = v;
    }
    // in-flight regs <- group 1 (rows base+16..31)   [R12 bug fix: group 1!]
    float4 rldg[8];
#pragma unroll
    for (int j = 0; j < 8; ++j)
        rldg[j] = __ldg((const float4*)(cldg + (size_t)(16 + 2 * j + ph) * CPITCH));
    const float* cnxt = cldg + (size_t)32 * CPITCH;   // group 2 (top of gi=0)
    __syncwarp();

    // boundary ring for group g: c0=[g-4..g-1], c1..c4=[g..g+15]
    float4 c0, c1, c2, c3, c4;
    if (cta > 0) {
        int need = base + 31 < flagmax ? base + 31 : flagmax;
        do { known = acq_load(pflag); } while (known < need);
        c0 = ldcg4(brow + base - 4);
        c1 = ldcg4(brow + base);
        c2 = ldcg4(brow + base + 4);
        c3 = ldcg4(brow + base + 8);
        c4 = ldcg4(brow + base + 12);
    } else {
        c0 = BIG4; c1 = BIG4; c2 = BIG4; c3 = BIG4; c4 = BIG4;
        c1.x = 0.0f;                       // virtual B[0] = R[0][0] = 0
    }

    float rA1 = BIGF, rB1 = BIGF;          // rows @ diag k-1
    float uA  = BIGF, uB  = BIGF;          // dg carries
    float sh  = BIGF;                      // shfl of rB1 from prev position
    float res = BIGF;

    const float* crd = &cbuf[0][0][0];
    float*       cwr = &cbuf[1][0][0];
    const int ll2 = 2 * lane;
    int g = base;
    int fnew = 0;
    float qv[16];

#pragma unroll 1
    for (int gi = 0; gi < 133; ++gi, g += 16) {
        // ---- group top ----
        // STS: regs (group gi+1) -> write buffer
#pragma unroll
        for (int j = 0; j < 8; ++j)
            *(float4*)(cwr + (2 * j + ph) * 64 + qf) = rldg[j];
        // LDG: group gi+2
#pragma unroll
        for (int j = 0; j < 8; ++j)
            rldg[j] = __ldg((const float4*)(cnxt + (size_t)(2 * j + ph) * CPITCH));
        cnxt += (size_t)16 * CPITCH;
        // boundary chunks for next group
        float4 n1 = (g + 16 <= wend) ? ldcg4(brow + g + 16) : BIG4;
        float4 n2 = (g + 20 <= wend) ? ldcg4(brow + g + 20) : BIG4;
        float4 n3 = (g + 24 <= wend) ? ldcg4(brow + g + 24) : BIG4;
        float4 n4 = (g + 28 <= wend) ? ldcg4(brow + g + 28) : BIG4;
        if (cta > 0) fnew = acq_load(pflag);

        float2 cnext = *(const float2*)(crd + ll2);   // position 0

#pragma unroll
        for (int p = 0; p < 16; ++p) {
            // bu = B[g-1+p]
            float bu = (p == 0)  ? c0.w :
                       (p == 1)  ? c1.x : (p == 2)  ? c1.y :
                       (p == 3)  ? c1.z : (p == 4)  ? c1.w :
                       (p == 5)  ? c2.x : (p == 6)  ? c2.y :
                       (p == 7)  ? c2.z : (p == 8)  ? c2.w :
                       (p == 9)  ? c3.x : (p == 10) ? c3.y :
                       (p == 11) ? c3.z : (p == 12) ? c3.w :
                       (p == 13) ? c4.x : (p == 14) ? c4.y : c4.z;

            float2 cost = cnext;
            if (p < 15) cnext = *(const float2*)(crd + (p + 1) * 64 + ll2);

            float upA = l0 ? bu : sh;
            float upB = rA1;                    // pre-update

            // softmin via ex2(0)=1: s = 1 + ex2(m-x) + ex2(m-y),
            // {x,y} = the two non-min neighbors (exact same arithmetic).
            float wA = fminf(upA, rA1), xA = fmaxf(upA, rA1);
            float wB = fminf(upB, rB1), xB = fmaxf(upB, rB1);
            float mA = fminf(wA, uA),   yA = fmaxf(wA, uA);
            float mB = fminf(wB, uB),   yB = fmaxf(wB, uB);

            float eA = ex2f(mA - xA) + ex2f(mA - yA);
            float eB = ex2f(mB - xB) + ex2f(mB - yB);
            float tA = lg2f(1.0f + eA);
            float tB = lg2f(1.0f + eB);

            uA  = upA; uB = upB;
            rA1 = (cost.x + mA) - tA;
            rB1 = (cost.y + mB) - tB;

            sh = __shfl_up_sync(0xffffffffu, rB1, 1);

            qv[p] = rB1;
            if (p == 0 && gi == 132) res = rB1;   // k = base+2112 (cta31: 4096)
        }

        // publish B[g..g+15], then flag
        if (l31) {
            stcg4(&g_bnd[cta][g],      make_float4(qv[0],  qv[1],  qv[2],  qv[3]));
            stcg4(&g_bnd[cta][g + 4],  make_float4(qv[4],  qv[5],  qv[6],  qv[7]));
            stcg4(&g_bnd[cta][g + 8],  make_float4(qv[8],  qv[9],  qv[10], qv[11]));
            stcg4(&g_bnd[cta][g + 12], make_float4(qv[12], qv[13], qv[14], qv[15]));
            rel_store(myflag, g + 15);
        }

        // fold + enforce: next top's loads reach chunk [g+44..g+47]
        if (cta > 0) {
            if (fnew > known) known = fnew;
            int need = g + 47 < flagmax ? g + 47 : flagmax;
            while (known < need) known = acq_load(pflag);
        }

        // rotate boundary ring; swap cost buffers
        c0 = c4; c1 = n1; c2 = n2; c3 = n3; c4 = n4;
        const float* tr = crd; crd = cwr; cwr = (float*)tr;
        __syncwarp();
    }

    if (cta == NCTA - 1 && l31) {
        out[0] = res * LN2F;
    }
}

// ---------------------------------------------------------------------------
extern "C" void kernel_launch(void* const* d_in, const int* in_sizes, int n_in,
                              void* d_out, int out_size) {
    const float* y  = (const float*)d_in[0];
    const float* x2 = (const float*)d_in[1];
    float* out = (float*)d_out;

    const int n4 = (CROWS * CPITCH) / 4;
    initc_k<<<(n4 + 1023) / 1024, 1024>>>();
    norms_k<<<512, 256>>>(y, x2);
    gemm_k<<<dim3(M2 / 64, M1 / 64), 256>>>(y, x2);
    dp_k<<<NCTA, 32>>>(out);
}

// round 14
// speedup vs baseline: 2.2427x; 1.5676x over previous
#include <cuda_runtime.h>
#include <cuda_bf16.h>
#include <cstdint>

// ---------------------------------------------------------------------------
// GMDTW (soft-DTW, gamma=1), m1=m2=2048, d=128. log2-domain DP.
// R14: warp-specialized DP. Each CTA = compute warp (pure ALU/MUFU/LDS/shfl)
// + helper warp (all LDG/STG/acquire/release/spin). Handoff via SMEM double
// buffers + one __syncthreads per 16-diag group. Indexing from proven R13.
// ---------------------------------------------------------------------------

#define M1 2048
#define M2 2048
#define DIM 128
#define NCTA 32
#define CPITCH 2080          // floats per diagonal row of Cd
#define CROWS  4176          // diagonal rows incl. staging overrun pad
#define BIGF 1e30f
#define INV_LN2 1.44269504088896340736f
#define LN2F    0.69314718055994530942f

__device__ float g_Cd[(size_t)CROWS * CPITCH];  // Cd[k][r] = C[r][k-r-2]*INV_LN2
__device__ float g_n1[M1];
__device__ float g_n2[M2];
__device__ float g_bnd[NCTA][4240];             // g_bnd[w][k] = R~[row 64(w+1)] @ diag k
__device__ int   g_prog[NCTA * 32];             // flag per 128B

__device__ __forceinline__ float ex2f(float x) {
    float r; asm("ex2.approx.f32 %0, %1;" : "=f"(r) : "f"(x)); return r;
}
__device__ __forceinline__ float lg2f(float x) {
    float r; asm("lg2.approx.f32 %0, %1;" : "=f"(r) : "f"(x)); return r;
}
__device__ __forceinline__ int acq_load(const int* p) {
    int v; asm volatile("ld.global.acquire.gpu.b32 %0, [%1];" : "=r"(v) : "l"(p) : "memory");
    return v;
}
__device__ __forceinline__ void rel_store(int* p, int v) {
    asm volatile("st.global.release.gpu.b32 [%0], %1;" :: "l"(p), "r"(v) : "memory");
}
__device__ __forceinline__ float4 ldcg4(const float* p) {
    float4 v;
    asm volatile("ld.global.cg.v4.f32 {%0,%1,%2,%3}, [%4];"
                 : "=f"(v.x), "=f"(v.y), "=f"(v.z), "=f"(v.w) : "l"(p) : "memory");
    return v;
}
__device__ __forceinline__ void stcg4(float* p, float4 v) {
    asm volatile("st.global.cg.v4.f32 [%0], {%1,%2,%3,%4};"
                 :: "l"(p), "f"(v.x), "f"(v.y), "f"(v.z), "f"(v.w) : "memory");
}

// ---------------------------------------------------------------------------
__global__ void __launch_bounds__(1024) initc_k() {
    size_t idx = (size_t)blockIdx.x * 1024 + threadIdx.x;
    const size_t n4 = (size_t)CROWS * CPITCH / 4;
    if (idx < n4) {
        ((float4*)g_Cd)[idx] = make_float4(BIGF, BIGF, BIGF, BIGF);
    }
    if (idx < NCTA * 32) g_prog[idx] = 0;
}

__global__ void __launch_bounds__(256) norms_k(const float* __restrict__ y,
                                               const float* __restrict__ x2) {
    int w = blockIdx.x * 8 + (threadIdx.x >> 5);
    int lane = threadIdx.x & 31;
    if (w >= 2 * M1) return;
    const float* src = (w < M1) ? (y + (size_t)w * DIM) : (x2 + (size_t)(w - M1) * DIM);
    float4 v = ((const float4*)src)[lane];
    float s = v.x * v.x + v.y * v.y + v.z * v.z + v.w * v.w;
#pragma unroll
    for (int o = 16; o; o >>= 1) s += __shfl_xor_sync(0xffffffffu, s, o);
    if (lane == 0) {
        if (w < M1) g_n1[w] = s; else g_n2[w - M1] = s;
    }
}

// GEMM with diagonal-major scatter epilogue: (r,c) -> Cd[r+c+2][r]
__global__ void __launch_bounds__(256) gemm_k(const float* __restrict__ A,
                                              const float* __restrict__ B) {
    __shared__ float As[32][68];
    __shared__ float Bs[32][68];
    const int t  = threadIdx.x;
    const int tx = t & 15, ty = t >> 4;
    const int bi = blockIdx.y << 6, bj = blockIdx.x << 6;
    const int lrow = t >> 2;
    const int lk   = (t & 3) << 3;

    float acc[4][4];
#pragma unroll
    for (int u = 0; u < 4; ++u)
#pragma unroll
        for (int v = 0; v < 4; ++v) acc[u][v] = 0.0f;

    const float* Ap = A + (size_t)(bi + lrow) * DIM + lk;
    const float* Bp = B + (size_t)(bj + lrow) * DIM + lk;

    for (int k0 = 0; k0 < DIM; k0 += 32) {
        float4 a0 = *(const float4*)(Ap + k0);
        float4 a1 = *(const float4*)(Ap + k0 + 4);
        float4 b0 = *(const float4*)(Bp + k0);
        float4 b1 = *(const float4*)(Bp + k0 + 4);
        __syncthreads();
        As[lk + 0][lrow] = a0.x; As[lk + 1][lrow] = a0.y;
        As[lk + 2][lrow] = a0.z; As[lk + 3][lrow] = a0.w;
        As[lk + 4][lrow] = a1.x; As[lk + 5][lrow] = a1.y;
        As[lk + 6][lrow] = a1.z; As[lk + 7][lrow] = a1.w;
        Bs[lk + 0][lrow] = b0.x; Bs[lk + 1][lrow] = b0.y;
        Bs[lk + 2][lrow] = b0.z; Bs[lk + 3][lrow] = b0.w;
        Bs[lk + 4][lrow] = b1.x; Bs[lk + 5][lrow] = b1.y;
        Bs[lk + 6][lrow] = b1.z; Bs[lk + 7][lrow] = b1.w;
        __syncthreads();
#pragma unroll
        for (int kk = 0; kk < 32; ++kk) {
            float4 av = *(const float4*)&As[kk][ty << 2];
            float4 bv = *(const float4*)&Bs[kk][tx << 2];
            float a_[4] = {av.x, av.y, av.z, av.w};
            float b_[4] = {bv.x, bv.y, bv.z, bv.w};
#pragma unroll
            for (int u = 0; u < 4; ++u)
#pragma unroll
                for (int v = 0; v < 4; ++v) acc[u][v] += a_[u] * b_[v];
        }
    }

    float4 nb = *(const float4*)&g_n2[bj + (tx << 2)];
#pragma unroll
    for (int u = 0; u < 4; ++u) {
        int r = bi + (ty << 2) + u;
        float na = g_n1[r];
        float o0 = (na + nb.x - 2.0f * acc[u][0]) * INV_LN2;
        float o1 = (na + nb.y - 2.0f * acc[u][1]) * INV_LN2;
        float o2 = (na + nb.z - 2.0f * acc[u][2]) * INV_LN2;
        float o3 = (na + nb.w - 2.0f * acc[u][3]) * INV_LN2;
        int c = bj + (tx << 2);
        g_Cd[(size_t)(r + c + 2) * CPITCH + r] = o0;
        g_Cd[(size_t)(r + c + 3) * CPITCH + r] = o1;
        g_Cd[(size_t)(r + c + 4) * CPITCH + r] = o2;
        g_Cd[(size_t)(r + c + 5) * CPITCH + r] = o3;
    }
}

// ---------------------------------------------------------------------------
// DP wavefront: 32 CTAs x 2 warps. Warp 0 = compute (64 rows, 2 rows/lane,
// 16-diag groups). Warp 1 = helper (staging + publish + flag protocol).
__global__ void __launch_bounds__(64, 1) dp_k(float* __restrict__ out) {
    const int cta  = blockIdx.x;
    const int tid  = threadIdx.x;
    const int wid  = tid >> 5;
    const int lane = tid & 31;
    const int base = cta * 64;

    __shared__ __align__(16) float  cbuf[2][16][64];  // costs, double-buffered
    __shared__ __align__(16) float4 sbch[2][5];       // boundary chunks (20 floats)
    __shared__ __align__(16) float  obuf[2][16];      // boundary outputs

    const float4 BIG4 = make_float4(BIGF, BIGF, BIGF, BIGF);

    const int  wend    = (cta > 0) ? (base + 2048) : -1;
    const int  flagmax = wend + 3;
    int*       myflag  = &g_prog[cta * 32];
    const int* pflag   = &g_prog[((cta > 0) ? (cta - 1) : 0) * 32];
    const float* brow  = g_bnd[(cta > 0) ? (cta - 1) : 0];

    // helper staging geometry (also used in prologue)
    const int ph = lane >> 4;              // 0/1
    const int qf = (lane & 15) << 2;       // float4 column

    // compute-warp state
    float rA1 = BIGF, rB1 = BIGF, uA = BIGF, uB = BIGF, sh = BIGF, res = BIGF;
    int known = -1000000;                  // helper-warp flag cache

    // ---- prologue (helper stages group 0) ----
    if (wid == 1) {
        const float* src = g_Cd + (size_t)base * CPITCH + base + qf;
#pragma unroll
        for (int j = 0; j < 8; ++j) {
            float4 v = __ldg((const float4*)(src + (size_t)(2 * j + ph) * CPITCH));
            *(float4*)&cbuf[0][2 * j + ph][qf] = v;
        }
        if (cta > 0) {
            int need = min(base + 15, flagmax);
            do { known = acq_load(pflag); } while (known < need);
        }
        if (lane < 5) {
            int cs = base - 4 + 4 * lane;
            sbch[0][lane] = (cta > 0 && cs <= wend) ? ldcg4(brow + cs) : BIG4;
        }
        if (cta == 0 && lane == 0)
            ((float*)&sbch[0][0])[4] = 0.0f;   // virtual B[0] = R[0][0] = 0
    }
    __syncthreads();

    const bool l0  = (lane == 0);
    const bool l31 = (lane == 31);
    const int  ll2 = 2 * lane;

    int g = base;
#pragma unroll 1
    for (int gi = 0; gi < 133; ++gi, g += 16) {
        const int a = gi & 1;
        const int b = a ^ 1;

        if (wid == 0) {
            // ================= COMPUTE WARP =================
            const float* crd = &cbuf[a][0][0];
            const float* bb  = ((const float*)&sbch[a][0]) + 3;  // bb[p] = B[g-1+p]
            float2 cnext = *(const float2*)(crd + ll2);
            float  bnext = bb[0];
            float  qv[16];

#pragma unroll
            for (int p = 0; p < 16; ++p) {
                float  bu   = bnext;
                float2 cost = cnext;
                if (p < 15) {
                    cnext = *(const float2*)(crd + (p + 1) * 64 + ll2);
                    bnext = bb[p + 1];
                }

                float upA = l0 ? bu : sh;
                float upB = rA1;                    // pre-update

                float wA = fminf(upA, rA1), xA = fmaxf(upA, rA1);
                float wB = fminf(upB, rB1), xB = fmaxf(upB, rB1);
                float mA = fminf(wA, uA),   yA = fmaxf(wA, uA);
                float mB = fminf(wB, uB),   yB = fmaxf(wB, uB);

                float eA = ex2f(mA - xA) + ex2f(mA - yA);
                float eB = ex2f(mB - xB) + ex2f(mB - yB);
                float tA = lg2f(1.0f + eA);
                float tB = lg2f(1.0f + eB);

                uA  = upA; uB = upB;
                rA1 = (cost.x + mA) - tA;
                rB1 = (cost.y + mB) - tB;

                sh = __shfl_up_sync(0xffffffffu, rB1, 1);

                qv[p] = rB1;
                if (p == 0 && gi == 132) res = rB1;   // k = base+2112 (cta31: 4096)
            }

            if (l31) {
                *(float4*)&obuf[a][0]  = make_float4(qv[0],  qv[1],  qv[2],  qv[3]);
                *(float4*)&obuf[a][4]  = make_float4(qv[4],  qv[5],  qv[6],  qv[7]);
                *(float4*)&obuf[a][8]  = make_float4(qv[8],  qv[9],  qv[10], qv[11]);
                *(float4*)&obuf[a][12] = make_float4(qv[12], qv[13], qv[14], qv[15]);
            }
        } else {
            // ================= HELPER WARP =================
            const int gnext = g + 16;
            // 1. publish group gi-1 (lane 0 only: release orders own stores)
            if (gi > 0 && lane == 0) {
                int gp = g - 16;
                float4 o0 = *(float4*)&obuf[b][0];
                float4 o1 = *(float4*)&obuf[b][4];
                float4 o2 = *(float4*)&obuf[b][8];
                float4 o3 = *(float4*)&obuf[b][12];
                stcg4(&g_bnd[cta][gp],      o0);
                stcg4(&g_bnd[cta][gp + 4],  o1);
                stcg4(&g_bnd[cta][gp + 8],  o2);
                stcg4(&g_bnd[cta][gp + 12], o3);
                rel_store(myflag, gp + 15);
            }
            // 2. cost LDGs for group gi+1 (rows gnext..gnext+15)
            const float* src = g_Cd + (size_t)gnext * CPITCH + base + qf;
            float4 tv[8];
#pragma unroll
            for (int j = 0; j < 8; ++j)
                tv[j] = __ldg((const float4*)(src + (size_t)(2 * j + ph) * CPITCH));
            // 3. acquire (spin lives here, off the critical warp)
            if (cta > 0) {
                int need = min(gnext + 15, flagmax);
                while (known < need) known = acq_load(pflag);
            }
            // 4. boundary chunks for gi+1
            if (lane < 5) {
                int cs = gnext - 4 + 4 * lane;
                sbch[b][lane] = (cta > 0 && cs <= wend) ? ldcg4(brow + cs) : BIG4;
            }
            // 5. STS costs (absorbs LDG latency)
#pragma unroll
            for (int j = 0; j < 8; ++j)
                *(float4*)&cbuf[b][2 * j + ph][qf] = tv[j];
        }

        __syncthreads();
    }

    // epilogue: publish final group (132, in obuf[0]) for the successor
    if (wid == 1 && lane == 0) {
        int gp = base + 16 * 132;
        float4 o0 = *(float4*)&obuf[0][0];
        float4 o1 = *(float4*)&obuf[0][4];
        float4 o2 = *(float4*)&obuf[0][8];
        float4 o3 = *(float4*)&obuf[0][12];
        stcg4(&g_bnd[cta][gp],      o0);
        stcg4(&g_bnd[cta][gp + 4],  o1);
        stcg4(&g_bnd[cta][gp + 8],  o2);
        stcg4(&g_bnd[cta][gp + 12], o3);
        rel_store(myflag, gp + 15);
    }

    if (wid == 0 && cta == NCTA - 1 && l31) {
        out[0] = res * LN2F;
    }
}

// ---------------------------------------------------------------------------
extern "C" void kernel_launch(void* const* d_in, const int* in_sizes, int n_in,
                              void* d_out, int out_size) {
    const float* y  = (const float*)d_in[0];
    const float* x2 = (const float*)d_in[1];
    float* out = (float*)d_out;

    const int n4 = (CROWS * CPITCH) / 4;
    initc_k<<<(n4 + 1023) / 1024, 1024>>>();
    norms_k<<<512, 256>>>(y, x2);
    gemm_k<<<dim3(M2 / 64, M1 / 64), 256>>>(y, x2);
    dp_k<<<NCTA, 64>>>(out);
}